// round 9
// baseline (speedup 1.0000x reference)
#include <cuda_runtime.h>
#include <cuda_bf16.h>
#include <cstdint>
#include <math.h>

// Problem dims
#define BB 256
#define TT 128
#define HH 1024
#define OO 47
#define PP 4
#define LL 3
#define GH 4096   // 4*H
#define KK 2048   // H (x part) + H (h part)

// GEMM tile config: BM=128 (batch), BN=64 (gate cols), BK=32, 512 threads (16 warps)
#define BM 128
#define BN 64
#define BK 32
#define NKT (KK / BK)        // 64 k-tiles
#define SMEM_BYTES 61440     // (128+64) rows * 40 elems * 2 prec * 2 stages * 2B

// ---------------- persistent device state ----------------
__device__ __nv_bfloat16 g_Whi[LL][GH][KK];
__device__ __nv_bfloat16 g_Wlo[LL][GH][KK];
__device__ float g_bias[LL][BB][GH];     // interleaved cols jp = 4*unit + gate
__device__ float g_c[LL][BB][HH];
__device__ float g_hf[LL][BB][HH];
__device__ __nv_bfloat16 g_hhi[2][LL][BB][HH];  // ping-pong h, hi part
__device__ __nv_bfloat16 g_hlo[2][LL][BB][HH];  // ping-pong h, lo part
__device__ __nv_bfloat16 g_xhi[BB][HH];
__device__ __nv_bfloat16 g_xlo[BB][HH];

__device__ __forceinline__ void split2(float v, __nv_bfloat16* hi, __nv_bfloat16* lo) {
    __nv_bfloat16 h = __float2bfloat16(v);
    *hi = h;
    *lo = __float2bfloat16(v - __bfloat162float(h));
}

// ---------------- setup kernels ----------------
__global__ void prep_weights(const float* __restrict__ Wih0,
                             const float* __restrict__ Wihr,
                             const float* __restrict__ Whh) {
    const int total = LL * GH * KK;
    for (int idx = blockIdx.x * 256 + threadIdx.x; idx < total; idx += gridDim.x * 256) {
        int k  = idx % KK;
        int jp = (idx / KK) % GH;
        int l  = idx / (KK * GH);
        int orig = (jp & 3) * HH + (jp >> 2);   // gate*1024 + unit
        float v;
        if (k < HH) {
            v = (l == 0) ? Wih0[(size_t)orig * (HH + PP) + k]
                         : Wihr[((size_t)(l - 1) * GH + orig) * HH + k];
        } else {
            v = Whh[((size_t)l * GH + orig) * HH + (k - HH)];
        }
        split2(v, &g_Whi[l][jp][k], &g_Wlo[l][jp][k]);
    }
}

__global__ void prep_bias(const float* __restrict__ props,
                          const float* __restrict__ bih,
                          const float* __restrict__ bhh,
                          const float* __restrict__ Wih0) {
    const int total = LL * BB * GH;
    for (int idx = blockIdx.x * 256 + threadIdx.x; idx < total; idx += gridDim.x * 256) {
        int jp = idx % GH;
        int b  = (idx / GH) % BB;
        int l  = idx / (GH * BB);
        int orig = (jp & 3) * HH + (jp >> 2);
        float v = bih[l * GH + orig] + bhh[l * GH + orig];
        if (l == 0) {
            #pragma unroll
            for (int p = 0; p < PP; p++)
                v += props[b * PP + p] * Wih0[(size_t)orig * (HH + PP) + HH + p];
        }
        g_bias[l][b][jp] = v;
    }
}

__global__ void init_state(const float* __restrict__ emb) {
    int idx = blockIdx.x * 256 + threadIdx.x;
    if (idx >= BB * HH) return;
    int b = idx / HH, k = idx % HH;
    #pragma unroll
    for (int l = 0; l < LL; l++) {
        g_c[l][b][k] = 0.f;
        g_hhi[0][l][b][k] = __float2bfloat16(0.f);
        g_hlo[0][l][b][k] = __float2bfloat16(0.f);
    }
    split2(emb[k], &g_xhi[b][k], &g_xlo[b][k]);
}

// ---------------- PTX helpers (sm_80-compatible only) ----------------
__device__ __forceinline__ void cp16(uint32_t dst, const void* src) {
    asm volatile("cp.async.cg.shared.global [%0], [%1], 16;\n" :: "r"(dst), "l"(src));
}
__device__ __forceinline__ void ldm_x4(uint32_t addr, uint32_t& r0, uint32_t& r1,
                                       uint32_t& r2, uint32_t& r3) {
    asm volatile("ldmatrix.sync.aligned.m8n8.x4.shared.b16 {%0,%1,%2,%3}, [%4];\n"
                 : "=r"(r0), "=r"(r1), "=r"(r2), "=r"(r3) : "r"(addr));
}
__device__ __forceinline__ void mma16816(float* c, const uint32_t* a, const uint32_t* b) {
    asm volatile("mma.sync.aligned.m16n8k16.row.col.f32.bf16.bf16.f32 "
                 "{%0,%1,%2,%3},{%4,%5,%6,%7},{%8,%9},{%0,%1,%2,%3};\n"
                 : "+f"(c[0]), "+f"(c[1]), "+f"(c[2]), "+f"(c[3])
                 : "r"(a[0]), "r"(a[1]), "r"(a[2]), "r"(a[3]), "r"(b[0]), "r"(b[1]));
}

// smem layout (bf16 units), rows padded to 40 elems (80B) for conflict-free ldmatrix
__device__ __forceinline__ int SA(int st, int pr, int r, int c) {
    return ((st * 2 + pr) * BM + r) * 40 + c;
}
__device__ __forceinline__ int SW(int st, int pr, int r, int c) {
    return 2 * 2 * BM * 40 + ((st * 2 + pr) * BN + r) * 40 + c;
}

// ---------------- fused GEMM + LSTM kernel (legacy mma.sync path) ----------------
__global__ __launch_bounds__(512, 1)
void lstm_layer_kernel(int l, int p) {
    extern __shared__ __nv_bfloat16 smem[];
    const int tid  = threadIdx.x;
    const int ctaN = blockIdx.x;   // 0..63 : 64 gate-cols = 16 units
    const int ctaM = blockIdx.y;   // 0..1  : 128 batch rows
    const int q = p ^ 1;

    const __nv_bfloat16* __restrict__ A0hi = (l == 0) ? &g_xhi[0][0] : &g_hhi[q][l - 1][0][0];
    const __nv_bfloat16* __restrict__ A0lo = (l == 0) ? &g_xlo[0][0] : &g_hlo[q][l - 1][0][0];
    const __nv_bfloat16* __restrict__ A1hi = &g_hhi[p][l][0][0];
    const __nv_bfloat16* __restrict__ A1lo = &g_hlo[p][l][0][0];
    const __nv_bfloat16* __restrict__ Whi  = &g_Whi[l][0][0];
    const __nv_bfloat16* __restrict__ Wlo  = &g_Wlo[l][0][0];

    uint32_t sbase;
    asm("{ .reg .u64 t; cvta.to.shared.u64 t, %1; cvt.u32.u64 %0, t; }"
        : "=r"(sbase) : "l"(smem));

    const int warp = tid >> 5, lane = tid & 31;
    const int wm = warp >> 2, wn = warp & 3;   // 4(M) x 4(N) warp grid; warp tile 32x16

    float acc[2][2][4];
    #pragma unroll
    for (int a = 0; a < 2; a++)
        #pragma unroll
        for (int b = 0; b < 2; b++)
            #pragma unroll
            for (int v = 0; v < 4; v++) acc[a][b][v] = 0.f;

    // loader: 1536 x 16B chunks, 3 per thread
    auto load_tile = [&](int kt, int st) {
        const int kg = kt * BK;
        #pragma unroll
        for (int t = 0; t < 3; t++) {
            const int idx = tid + t * 512;
            if (idx < 1024) {          // A: 128 rows x 4 chunks x 2 prec
                const int pr = idx >> 9;
                const int r  = (idx >> 2) & 127;
                const int c  = idx & 3;
                const int k  = kg + c * 8;
                const __nv_bfloat16* bsrc = (k < HH) ? (pr ? A0lo : A0hi)
                                                     : (pr ? A1lo : A1hi);
                const int kk = k & (HH - 1);
                cp16(sbase + 2u * SA(st, pr, r, c * 8),
                     bsrc + (size_t)(ctaM * BM + r) * HH + kk);
            } else {                   // W: 64 rows x 4 chunks x 2 prec
                const int j  = idx - 1024;
                const int pr = j >> 8;
                const int r  = (j >> 2) & 63;
                const int c  = j & 3;
                const int k  = kg + c * 8;
                cp16(sbase + 2u * SW(st, pr, r, c * 8),
                     (pr ? Wlo : Whi) + (size_t)(ctaN * BN + r) * KK + k);
            }
        }
        asm volatile("cp.async.commit_group;\n");
    };

    load_tile(0, 0);

    for (int kt = 0; kt < NKT; kt++) {
        const int st = kt & 1;
        asm volatile("cp.async.wait_group 0;\n");
        __syncthreads();                      // tile kt resident; prev compute done
        if (kt + 1 < NKT) load_tile(kt + 1, st ^ 1);

        // load both kf fragment sets, then MMA burst
        uint32_t ahi[2][2][4], alo[2][2][4], bhi[2][2][2], blo[2][2][2];
        #pragma unroll
        for (int kf = 0; kf < 2; kf++) {
            #pragma unroll
            for (int mf = 0; mf < 2; mf++) {
                const int r = wm * 32 + mf * 16 + (lane & 15);
                const int c = kf * 16 + ((lane >> 4) & 1) * 8;
                ldm_x4(sbase + 2u * SA(st, 0, r, c),
                       ahi[kf][mf][0], ahi[kf][mf][1], ahi[kf][mf][2], ahi[kf][mf][3]);
                ldm_x4(sbase + 2u * SA(st, 1, r, c),
                       alo[kf][mf][0], alo[kf][mf][1], alo[kf][mf][2], alo[kf][mf][3]);
            }
            const int r = wn * 16 + (lane & 7) + ((lane >> 4) & 1) * 8;
            const int c = kf * 16 + ((lane >> 3) & 1) * 8;
            uint32_t r0, r1, r2, r3;
            ldm_x4(sbase + 2u * SW(st, 0, r, c), r0, r1, r2, r3);
            bhi[kf][0][0] = r0; bhi[kf][0][1] = r1;
            bhi[kf][1][0] = r2; bhi[kf][1][1] = r3;
            ldm_x4(sbase + 2u * SW(st, 1, r, c), r0, r1, r2, r3);
            blo[kf][0][0] = r0; blo[kf][0][1] = r1;
            blo[kf][1][0] = r2; blo[kf][1][1] = r3;
        }
        #pragma unroll
        for (int kf = 0; kf < 2; kf++)
            #pragma unroll
            for (int mf = 0; mf < 2; mf++)
                #pragma unroll
                for (int nf = 0; nf < 2; nf++) {
                    mma16816(acc[mf][nf], ahi[kf][mf], bhi[kf][nf]);  // hi*hi
                    mma16816(acc[mf][nf], ahi[kf][mf], blo[kf][nf]);  // hi*lo
                    mma16816(acc[mf][nf], alo[kf][mf], bhi[kf][nf]);  // lo*hi
                }
    }

    // epilogue: stage gates in smem, then fused LSTM update
    __syncthreads();                                  // frag reads done; smem reusable
    float* gs  = reinterpret_cast<float*>(smem);      // [BM][BN] = 32KB
    float* s_c = gs + BM * BN;                        // [128][16]
    float* s_h = s_c + BM * 16;                       // [128][16]
    #pragma unroll
    for (int mf = 0; mf < 2; mf++)
        #pragma unroll
        for (int nf = 0; nf < 2; nf++) {
            const int r = wm * 32 + mf * 16 + (lane >> 2);
            const int c = wn * 16 + nf * 8 + (lane & 3) * 2;
            gs[r * BN + c]           = acc[mf][nf][0];
            gs[r * BN + c + 1]       = acc[mf][nf][1];
            gs[(r + 8) * BN + c]     = acc[mf][nf][2];
            gs[(r + 8) * BN + c + 1] = acc[mf][nf][3];
        }
    __syncthreads();

    for (int it = tid; it < BM * 16; it += 512) {
        const int row = it >> 4, u = it & 15;
        const int b  = ctaM * BM + row;
        const int hu = ctaN * 16 + u;
        const float* bptr = &g_bias[l][b][ctaN * BN + u * 4];
        const float gi = gs[row * BN + u * 4 + 0] + bptr[0];
        const float gf = gs[row * BN + u * 4 + 1] + bptr[1];
        const float gg = gs[row * BN + u * 4 + 2] + bptr[2];
        const float go = gs[row * BN + u * 4 + 3] + bptr[3];
        const float si = 1.f / (1.f + expf(-gi));
        const float sf = 1.f / (1.f + expf(-gf));
        const float so = 1.f / (1.f + expf(-go));
        const float cn = sf * g_c[l][b][hu] + si * tanhf(gg);
        const float hn = so * tanhf(cn);
        s_c[row * 16 + u] = cn;
        s_h[row * 16 + u] = hn;
    }
    __syncthreads();

    if (tid < BM) {   // coalesced 16B writes: 16 contiguous units per batch row
        const int b = ctaM * BM + tid;
        const int h0 = ctaN * 16;
        float4* cdst = reinterpret_cast<float4*>(&g_c[l][b][h0]);
        float4* hdst = reinterpret_cast<float4*>(&g_hf[l][b][h0]);
        const float4* cs = reinterpret_cast<const float4*>(&s_c[tid * 16]);
        const float4* hs = reinterpret_cast<const float4*>(&s_h[tid * 16]);
        #pragma unroll
        for (int k = 0; k < 4; k++) { cdst[k] = cs[k]; hdst[k] = hs[k]; }
        __nv_bfloat16 hh[16], hl[16];
        #pragma unroll
        for (int k = 0; k < 16; k++) split2(s_h[tid * 16 + k], &hh[k], &hl[k]);
        uint4* hhid = reinterpret_cast<uint4*>(&g_hhi[q][l][b][h0]);
        uint4* hlod = reinterpret_cast<uint4*>(&g_hlo[q][l][b][h0]);
        const uint4* hhs = reinterpret_cast<const uint4*>(hh);
        const uint4* hls = reinterpret_cast<const uint4*>(hl);
        hhid[0] = hhs[0]; hhid[1] = hhs[1];
        hlod[0] = hls[0]; hlod[1] = hls[1];
    }
}

// ---------------- decode: logits + argmax + embed next token ----------------
__global__ __launch_bounds__(128)
void decode_kernel(const float* __restrict__ Wdec, const float* __restrict__ bdec,
                   const float* __restrict__ emb, float* __restrict__ out, int t) {
    __shared__ float4 sh4[HH / 4];
    __shared__ float sl[OO];
    __shared__ int snxt;
    const int b = blockIdx.x, tid = threadIdx.x;
    const float4* __restrict__ h4 = reinterpret_cast<const float4*>(&g_hf[LL - 1][b][0]);
    for (int k = tid; k < HH / 4; k += 128) sh4[k] = h4[k];
    __syncthreads();
    const int w = tid >> 5, lane = tid & 31;
    for (int o = w; o < OO; o += 4) {
        const float4* wr = reinterpret_cast<const float4*>(Wdec + (size_t)o * HH);
        float s = 0.f;
        for (int k = lane; k < HH / 4; k += 32) {
            float4 a = sh4[k], c = wr[k];
            s += a.x * c.x + a.y * c.y + a.z * c.z + a.w * c.w;
        }
        #pragma unroll
        for (int off = 16; off; off >>= 1) s += __shfl_xor_sync(0xffffffffu, s, off);
        if (lane == 0) sl[o] = s + bdec[o];
    }
    __syncthreads();
    if (tid < OO) out[((size_t)b * TT + t) * OO + tid] = sl[tid];
    if (tid == 0) {
        float best = sl[0]; int bi = 0;
        #pragma unroll
        for (int o = 1; o < OO; o++)
            if (sl[o] > best) { best = sl[o]; bi = o; }
        snxt = bi;
    }
    __syncthreads();
    const float* er = emb + (size_t)snxt * HH;
    for (int k = tid; k < HH; k += 128) split2(er[k], &g_xhi[b][k], &g_xlo[b][k]);
}

// ---------------- final h/c copy into output ----------------
__global__ void final_copy(float* __restrict__ out) {
    const int LBH = LL * BB * HH;
    float* dst = out + (size_t)BB * TT * OO;
    const float* hsrc = &g_hf[0][0][0];
    const float* csrc = &g_c[0][0][0];
    for (int idx = blockIdx.x * 256 + threadIdx.x; idx < 2 * LBH; idx += gridDim.x * 256) {
        dst[idx] = (idx < LBH) ? hsrc[idx] : csrc[idx - LBH];
    }
}

// ---------------- host launcher ----------------
extern "C" void kernel_launch(void* const* d_in, const int* in_sizes, int n_in,
                              void* d_out, int out_size) {
    const float* props = (const float*)d_in[1];
    const float* emb   = (const float*)d_in[2];
    const float* Wdec  = (const float*)d_in[3];
    const float* bdec  = (const float*)d_in[4];
    const float* Wih0  = (const float*)d_in[5];
    const float* Wihr  = (const float*)d_in[6];
    const float* Whh   = (const float*)d_in[7];
    const float* bih   = (const float*)d_in[8];
    const float* bhh   = (const float*)d_in[9];
    float* out = (float*)d_out;

    cudaFuncSetAttribute(lstm_layer_kernel,
                         cudaFuncAttributeMaxDynamicSharedMemorySize, SMEM_BYTES);

    prep_weights<<<8192, 256>>>(Wih0, Wihr, Whh);
    prep_bias<<<4096, 256>>>(props, bih, bhh, Wih0);
    init_state<<<(BB * HH + 255) / 256, 256>>>(emb);

    dim3 grid(GH / BN, BB / BM);  // (64, 2) = 128 CTAs
    for (int t = 0; t < TT; t++) {
        const int p = t & 1;
        for (int l = 0; l < LL; l++)
            lstm_layer_kernel<<<grid, 512, SMEM_BYTES>>>(l, p);
        decode_kernel<<<BB, 128>>>(Wdec, bdec, emb, out, t);
    }
    final_copy<<<4096, 256>>>(out);
}